// round 6
// baseline (speedup 1.0000x reference)
#include <cuda_runtime.h>
#include <stdint.h>
#include <math.h>

#define T_FRAMES   3000
#define F_BINS     201
#define FSTRIDE    (F_BINS * 2)         // floats per frame
#define BATCH      32
#define CHUNK      375
#define CHUNKS     (T_FRAMES / CHUNK)   // 8
#define HALO       60                   // >= 40 needed; 60 keeps warm-up mod-30
#define NTHREADS   224
#define NWARPS     (NTHREADS / 32)
#define EPS_F      1e-5f
#define LOG10_2    0.30102999566398f    // log10(2): converts log2 diffs to log10
#define PDEPTH     10                   // register prefetch depth (30 % 10 == 0)

// One scan step. J compile-time (fully unrolled) so ALL ring indices are
// immediates and rings live in fixed registers (every ring length divides 30,
// so registers are consistent at group boundaries). Data comes from the
// register prefetch ring pre[PDEPTH]: consume slot, immediately re-issue the
// LDG for frame t+PDEPTH into the same slot -> PDEPTH loads always in flight.
#define STEP(J, TT, RC10, RC30, DO_SUB, EMIT)                                    \
  do {                                                                           \
    const int t_ = (TT);                                                         \
    const float2 xv = pre[(J) % PDEPTH];                                         \
    {                                                                            \
      const int tp_ = min(t_ + PDEPTH, T_FRAMES - 1);                            \
      pre[(J) % PDEPTH] = *(const float2*)(xbase + (size_t)tp_ * FSTRIDE);       \
    }                                                                            \
    const float s_t = (xv.x * xv.x + xv.y * xv.y) * Cf;                          \
    const float welch_t = (t_ == 0) ? 0.f : sum_s * (RC10);                      \
    const float lw2_t = __log2f(welch_t + EPS_F);                                \
    if (EMIT) {                                                                  \
      float contrib = 0.f;                                                       \
      if (active && t_ > 0) {                                                    \
        const float am   = fmaf(sum_w, (RC30), EPS_F);                           \
        const float mlw2 = sum_lw2 * (RC30);                                     \
        contrib = (__log2f(am) - mlw2) * LOG10_2;                                \
      }                                                                          \
      buf[J][tid] = contrib;                                                     \
    }                                                                            \
    if (DO_SUB) {                                                                \
      sum_w   += welch_t - ring_w[(J) % 30];                                     \
      sum_lw2 += lw2_t   - ring_lw[(J) % 30];                                    \
    } else {                                                                     \
      sum_w   += welch_t;                                                        \
      sum_lw2 += lw2_t;                                                          \
    }                                                                            \
    ring_w[(J) % 30]  = welch_t;                                                 \
    ring_lw[(J) % 30] = lw2_t;                                                   \
    sum_s += s_t - ring_s[(J) % 10];                                             \
    ring_s[(J) % 10] = s_t;                                                      \
  } while (0)

// Batched cross-thread reduction of one 30-frame group (block-uniform emit).
// Frames past chunk_end are computed but not written (next chunk owns them),
// so CHUNK need not be a multiple of 30.
#define REDUCE_GROUP(TB)                                                         \
  do {                                                                           \
    __syncthreads();                                                             \
    for (int j_ = warp; j_ < 30; j_ += NWARPS) {                                 \
      float v_ = 0.f;                                                            \
      _Pragma("unroll")                                                          \
      for (int i_ = 0; i_ < NTHREADS / 32; i_++)                                 \
        v_ += buf[j_][lane + 32 * i_];                                           \
      _Pragma("unroll")                                                          \
      for (int off_ = 16; off_ > 0; off_ >>= 1)                                  \
        v_ += __shfl_xor_sync(0xffffffffu, v_, off_);                            \
      if (lane == 0 && (TB) + j_ < chunk_end)                                    \
        out[(size_t)b * T_FRAMES + (TB) + j_] = v_;                              \
    }                                                                            \
    __syncthreads();                                                             \
  } while (0)

__global__ __launch_bounds__(NTHREADS, 2)
void ltsf_kernel(const float* __restrict__ x, float* __restrict__ out,
                 const float cA) {
  const int unit = blockIdx.x;
  const int b = unit / CHUNKS;
  const int c = unit % CHUNKS;
  const int chunk_start = c * CHUNK;
  const int chunk_end = chunk_start + CHUNK;
  const int t_begin = (c == 0) ? 0 : (chunk_start - HALO);

  const int tid  = threadIdx.x;
  const int f    = tid;
  const bool active = (f < F_BINS);
  const int lane = tid & 31;
  const int warp = tid >> 5;

  __shared__ float buf[30][NTHREADS];   // contrib tile (26.9 KB)

  // per-bin scale: interior bins doubled (welch one-sided spectrum)
  const float Cf = (f == 0 || f == F_BINS - 1) ? cA : 2.0f * cA;

  // inactive threads stream bin 0 (harmless; contrib is masked)
  const int fsel = active ? f : 0;
  const float* xbase =
      x + (size_t)b * T_FRAMES * FSTRIDE + (size_t)fsel * 2;

  // register-resident rings (indices compile-time via full unroll)
  float2 pre[PDEPTH];
  float ring_s[10];
  float ring_w[30];
  float ring_lw[30];
  float sum_s = 0.f, sum_w = 0.f, sum_lw2 = 0.f;
#pragma unroll
  for (int i = 0; i < 10; i++) ring_s[i] = 0.f;
#pragma unroll
  for (int i = 0; i < 30; i++) { ring_w[i] = 0.f; ring_lw[i] = 0.f; }

  // ---- prefetch prologue: frames t_begin .. t_begin+PDEPTH-1 ----
#pragma unroll
  for (int p = 0; p < PDEPTH; p++)
    pre[p] = *(const float2*)(xbase + (size_t)(t_begin + p) * FSTRIDE);

  // ---- warm-up group: first 30 frames of the scan, no ring subtraction ----
  // c==0: real frames with exact ramp-up divisors (compile-time j == t).
  // c>0: halo frames; state stabilizes before emission (HALO=60 > 40).
  {
    const bool emit0 = (c == 0);
#pragma unroll
    for (int j = 0; j < 30; j++) {
      const int cj10 = (j < 1) ? 1 : (j > 10 ? 10 : j);
      const int cj30 = (j < 1) ? 1 : j;
      const float rc10 = 1.0f / (float)cj10;
      const float rc30 = 1.0f / (float)cj30;
      STEP(j, t_begin + j, rc10, rc30, false, emit0);
    }
    if (emit0) REDUCE_GROUP(t_begin);
  }

  // ---- steady groups: counts are constant 10 / 30 ----
  for (int tb = t_begin + 30; tb < chunk_end; tb += 30) {
    const bool emit = (tb + 29 >= chunk_start);  // block-uniform
#pragma unroll
    for (int j = 0; j < 30; j++) {
      STEP(j, tb + j, 0.1f, (1.0f / 30.0f), true, emit);
    }
    if (emit) REDUCE_GROUP(tb);
  }
}

extern "C" void kernel_launch(void* const* d_in, const int* in_sizes, int n_in,
                              void* d_out, int out_size) {
  (void)in_sizes; (void)n_in; (void)out_size;
  // hamming_sq_sum(25), periodic: sum((0.54 - 0.46*cos(2*pi*k/25))^2)
  double h = 0.0;
  for (int k = 0; k < 25; k++) {
    double w = 0.54 - 0.46 * cos(2.0 * M_PI * (double)k / 25.0);
    h += w * w;
  }
  // fold the /M (spectr) and /SAMPLE_RATE (welch) into one per-bin constant
  const float cA = (float)(h / 16000.0 / 10.0);

  const float* x = (const float*)d_in[0];
  float* out = (float*)d_out;
  ltsf_kernel<<<BATCH * CHUNKS, NTHREADS>>>(x, out, cA);
}

// round 7
// speedup vs baseline: 1.0226x; 1.0226x over previous
#include <cuda_runtime.h>
#include <stdint.h>
#include <math.h>

#define T_FRAMES   3000
#define F_BINS     201
#define FSTRIDE    (F_BINS * 2)         // floats per frame
#define BATCH      32
#define CHUNK      250
#define CHUNKS     (T_FRAMES / CHUNK)   // 12
#define HALO       60                   // >= 40 needed; 60 keeps warm-up mod-30
#define NTHREADS   224
#define NWARPS     (NTHREADS / 32)
#define EPS_F      1e-5f
#define LOG10_2    0.30102999566398f    // log10(2): converts log2 diffs to log10
#define PDEPTH     10                   // LDG prefetch depth (divides 30)

// One scan step. J compile-time (fully unrolled) so ALL ring indices are
// immediates and rings live in fixed registers (ring lengths divide 30, so
// register assignment is consistent at group boundaries). Data comes from the
// register prefetch ring pre[PDEPTH]: consume slot, immediately re-issue the
// LDG for frame t+PDEPTH into the same slot -> PDEPTH loads always in flight.
// Eviction log is RECOMPUTED (1 extra MUFU) instead of stored (30 registers) --
// that tradeoff is what sank round 6.
#define STEP(J, TT, RC10, RC30, DO_SUB, EMIT)                                    \
  do {                                                                           \
    const int t_ = (TT);                                                         \
    const float2 xv = pre[(J) % PDEPTH];                                         \
    {                                                                            \
      const int tp_ = min(t_ + PDEPTH, T_FRAMES - 1);                            \
      pre[(J) % PDEPTH] = *(const float2*)(xbase + (size_t)tp_ * FSTRIDE);       \
    }                                                                            \
    const float s_t = (xv.x * xv.x + xv.y * xv.y) * Cf;                          \
    const float welch_t = (t_ == 0) ? 0.f : sum_s * (RC10);                      \
    const float lw2_t = __log2f(welch_t + EPS_F);                                \
    if (EMIT) {                                                                  \
      float contrib = 0.f;                                                       \
      if (active && t_ > 0) {                                                    \
        const float am   = fmaf(sum_w, (RC30), EPS_F);                           \
        const float mlw2 = sum_lw2 * (RC30);                                     \
        contrib = (__log2f(am) - mlw2) * LOG10_2;                                \
      }                                                                          \
      buf[J][tid] = contrib;                                                     \
    }                                                                            \
    if (DO_SUB) {                                                                \
      const float w_old = ring_w[(J) % 30];                                      \
      sum_w   += welch_t - w_old;                                                \
      sum_lw2 += lw2_t - __log2f(w_old + EPS_F);                                 \
    } else {                                                                     \
      sum_w   += welch_t;                                                        \
      sum_lw2 += lw2_t;                                                          \
    }                                                                            \
    ring_w[(J) % 30] = welch_t;                                                  \
    sum_s += s_t - ring_s[(J) % 10];                                             \
    ring_s[(J) % 10] = s_t;                                                      \
  } while (0)

// Batched cross-thread reduction of one 30-frame group (block-uniform emit).
// Frames past chunk_end are computed but not written (next chunk owns them),
// so CHUNK need not be a multiple of 30 and overrun past T_FRAMES is safe
// (loads are clamped, writes are masked).
#define REDUCE_GROUP(TB)                                                         \
  do {                                                                           \
    __syncthreads();                                                             \
    for (int j_ = warp; j_ < 30; j_ += NWARPS) {                                 \
      float v_ = 0.f;                                                            \
      _Pragma("unroll")                                                          \
      for (int i_ = 0; i_ < NTHREADS / 32; i_++)                                 \
        v_ += buf[j_][lane + 32 * i_];                                           \
      _Pragma("unroll")                                                          \
      for (int off_ = 16; off_ > 0; off_ >>= 1)                                  \
        v_ += __shfl_xor_sync(0xffffffffu, v_, off_);                            \
      if (lane == 0 && (TB) + j_ < chunk_end)                                    \
        out[(size_t)b * T_FRAMES + (TB) + j_] = v_;                              \
    }                                                                            \
    __syncthreads();                                                             \
  } while (0)

__global__ __launch_bounds__(NTHREADS, 3)
void ltsf_kernel(const float* __restrict__ x, float* __restrict__ out,
                 const float cA) {
  const int unit = blockIdx.x;
  const int b = unit / CHUNKS;
  const int c = unit % CHUNKS;
  const int chunk_start = c * CHUNK;
  const int chunk_end = chunk_start + CHUNK;
  const int t_begin = (c == 0) ? 0 : (chunk_start - HALO);

  const int tid  = threadIdx.x;
  const int f    = tid;
  const bool active = (f < F_BINS);
  const int lane = tid & 31;
  const int warp = tid >> 5;

  __shared__ float buf[30][NTHREADS];   // contrib tile (26.9 KB)

  // per-bin scale: interior bins doubled (welch one-sided spectrum)
  const float Cf = (f == 0 || f == F_BINS - 1) ? cA : 2.0f * cA;

  // inactive threads stream bin 0 (harmless; contrib is masked)
  const int fsel = active ? f : 0;
  const float* xbase =
      x + (size_t)b * T_FRAMES * FSTRIDE + (size_t)fsel * 2;

  // register-resident rings (indices compile-time via full unroll)
  float2 pre[PDEPTH];
  float ring_s[10];
  float ring_w[30];
  float sum_s = 0.f, sum_w = 0.f, sum_lw2 = 0.f;
#pragma unroll
  for (int i = 0; i < 10; i++) ring_s[i] = 0.f;
#pragma unroll
  for (int i = 0; i < 30; i++) ring_w[i] = 0.f;

  // ---- prefetch prologue: frames t_begin .. t_begin+PDEPTH-1 ----
#pragma unroll
  for (int p = 0; p < PDEPTH; p++)
    pre[p] = *(const float2*)(xbase + (size_t)(t_begin + p) * FSTRIDE);

  // ---- warm-up group: first 30 frames of the scan, no ring subtraction ----
  // c==0: real frames with exact ramp-up divisors (compile-time j == t).
  // c>0: halo frames; state stabilizes before emission (HALO=60 > 40).
  {
    const bool emit0 = (c == 0);
#pragma unroll
    for (int j = 0; j < 30; j++) {
      const int cj10 = (j < 1) ? 1 : (j > 10 ? 10 : j);
      const int cj30 = (j < 1) ? 1 : j;
      const float rc10 = 1.0f / (float)cj10;
      const float rc30 = 1.0f / (float)cj30;
      STEP(j, t_begin + j, rc10, rc30, false, emit0);
    }
    if (emit0) REDUCE_GROUP(t_begin);
  }

  // ---- steady groups: counts are constant 10 / 30 ----
  for (int tb = t_begin + 30; tb < chunk_end; tb += 30) {
    const bool emit = (tb + 29 >= chunk_start);  // block-uniform
#pragma unroll
    for (int j = 0; j < 30; j++) {
      STEP(j, tb + j, 0.1f, (1.0f / 30.0f), true, emit);
    }
    if (emit) REDUCE_GROUP(tb);
  }
}

extern "C" void kernel_launch(void* const* d_in, const int* in_sizes, int n_in,
                              void* d_out, int out_size) {
  (void)in_sizes; (void)n_in; (void)out_size;
  // hamming_sq_sum(25), periodic: sum((0.54 - 0.46*cos(2*pi*k/25))^2)
  double h = 0.0;
  for (int k = 0; k < 25; k++) {
    double w = 0.54 - 0.46 * cos(2.0 * M_PI * (double)k / 25.0);
    h += w * w;
  }
  // fold the /M (spectr) and /SAMPLE_RATE (welch) into one per-bin constant
  const float cA = (float)(h / 16000.0 / 10.0);

  const float* x = (const float*)d_in[0];
  float* out = (float*)d_out;
  ltsf_kernel<<<BATCH * CHUNKS, NTHREADS>>>(x, out, cA);
}

// round 8
// speedup vs baseline: 1.3609x; 1.3308x over previous
#include <cuda_runtime.h>
#include <stdint.h>
#include <math.h>

#define T_FRAMES   3000
#define F_BINS     201
#define FSTRIDE    (F_BINS * 2)         // floats per frame
#define BATCH      32
#define CHUNK      334
#define CHUNKS     9                    // 9*334 = 3006 >= 3000; last chunk short
#define HALO       60                   // >= 40 needed; 60 keeps warm-up mod-30
#define NTHREADS   224
#define NWARPS     (NTHREADS / 32)
#define EPS_F      1e-5f
#define LOG10_2    0.30102999566398f    // log10(2): converts log2 diffs to log10
#define PIPE_DEPTH 8                    // cp.async groups in flight
#define NSLOTS     10                   // smem ring slots (30 % 10 == 0)

__device__ __forceinline__ void cp_async8(uint32_t smem_addr, const float* gptr) {
  asm volatile("cp.async.ca.shared.global [%0], [%1], 8;\n"
               :: "r"(smem_addr), "l"(gptr));
}
#define CP_COMMIT() asm volatile("cp.async.commit_group;\n" ::: "memory")
#define CP_WAIT7()  asm volatile("cp.async.wait_group 7;\n" ::: "memory")

// One scan step. J compile-time (unrolled) so rings stay in registers and the
// smem slot index is an immediate. Data comes from the cp.async smem ring;
// each thread reads/writes only its own slot column -> no cross-thread sync.
// All logs are base-2; the final contrib is scaled once by log10(2).
#define STEP(J, TT, RC10, RC30, DO_SUB, EMIT)                                    \
  do {                                                                           \
    const int t_ = (TT);                                                         \
    CP_WAIT7();                                                                  \
    float2 xv = stage[(J) % NSLOTS][tid];                                        \
    {                                                                            \
      const int tp_ = min(t_ + PIPE_DEPTH, T_FRAMES - 1);                        \
      cp_async8(slot0 + (((J) + PIPE_DEPTH) % NSLOTS) * (NTHREADS * 8),          \
                xbase + (size_t)tp_ * FSTRIDE);                                  \
    }                                                                            \
    CP_COMMIT();                                                                 \
    const float s_t = (xv.x * xv.x + xv.y * xv.y) * Cf;                          \
    const float welch_t = (t_ == 0) ? 0.f : sum_s * (RC10);                      \
    const float lw2_t = __log2f(welch_t + EPS_F);                                \
    if (EMIT) {                                                                  \
      float contrib = 0.f;                                                       \
      if (active && t_ > 0) {                                                    \
        const float am   = fmaf(sum_w, (RC30), EPS_F);                           \
        const float mlw2 = sum_lw2 * (RC30);                                     \
        contrib = (__log2f(am) - mlw2) * LOG10_2;                                \
      }                                                                          \
      buf[J][tid] = contrib;                                                     \
    }                                                                            \
    if (DO_SUB) {                                                                \
      const float w_old = ring_w[(J) % 30];                                      \
      sum_w   += welch_t - w_old;                                                \
      sum_lw2 += lw2_t - __log2f(w_old + EPS_F);                                 \
    } else {                                                                     \
      sum_w   += welch_t;                                                        \
      sum_lw2 += lw2_t;                                                          \
    }                                                                            \
    ring_w[(J) % 30] = welch_t;                                                  \
    sum_s += s_t - ring_s[(J) % 10];                                             \
    ring_s[(J) % 10] = s_t;                                                      \
  } while (0)

// Batched cross-thread reduction of one 30-frame group (block-uniform emit).
// Frames past chunk_end are computed but not written (next chunk owns them, or
// they're past T_FRAMES) -- CHUNK need not divide T or be a multiple of 30.
#define REDUCE_GROUP(TB)                                                         \
  do {                                                                           \
    __syncthreads();                                                             \
    for (int j_ = warp; j_ < 30; j_ += NWARPS) {                                 \
      float v_ = 0.f;                                                            \
      _Pragma("unroll")                                                          \
      for (int i_ = 0; i_ < NTHREADS / 32; i_++)                                 \
        v_ += buf[j_][lane + 32 * i_];                                           \
      _Pragma("unroll")                                                          \
      for (int off_ = 16; off_ > 0; off_ >>= 1)                                  \
        v_ += __shfl_xor_sync(0xffffffffu, v_, off_);                            \
      if (lane == 0 && (TB) + j_ < chunk_end)                                    \
        out[(size_t)b * T_FRAMES + (TB) + j_] = v_;                              \
    }                                                                            \
    __syncthreads();                                                             \
  } while (0)

__global__ __launch_bounds__(NTHREADS, 4)
void ltsf_kernel(const float* __restrict__ x, float* __restrict__ out,
                 const float cA) {
  const int unit = blockIdx.x;
  const int b = unit / CHUNKS;
  const int c = unit % CHUNKS;
  const int chunk_start = c * CHUNK;
  const int chunk_end = min(chunk_start + CHUNK, T_FRAMES);
  const int t_begin = (c == 0) ? 0 : (chunk_start - HALO);

  const int tid  = threadIdx.x;
  const int f    = tid;
  const bool active = (f < F_BINS);
  const int lane = tid & 31;
  const int warp = tid >> 5;

  __shared__ float2 stage[NSLOTS][NTHREADS];  // cp.async ring (17.9 KB)
  __shared__ float  buf[30][NTHREADS];        // contrib tile (26.9 KB)

  // per-bin scale: interior bins doubled (welch one-sided spectrum)
  const float Cf = (f == 0 || f == F_BINS - 1) ? cA : 2.0f * cA;

  // inactive threads stream bin 0 (harmless; contrib is masked)
  const int fsel = active ? f : 0;
  const float* xbase =
      x + (size_t)b * T_FRAMES * FSTRIDE + (size_t)fsel * 2;
  const uint32_t slot0 = (uint32_t)__cvta_generic_to_shared(&stage[0][tid]);

  // register-resident ring buffers (indices compile-time via full unroll)
  float ring_s[10];
  float ring_w[30];
  float sum_s = 0.f, sum_w = 0.f, sum_lw2 = 0.f;
#pragma unroll
  for (int i = 0; i < 10; i++) ring_s[i] = 0.f;
#pragma unroll
  for (int i = 0; i < 30; i++) ring_w[i] = 0.f;

  // ---- pipeline prologue: frames t_begin .. t_begin+PIPE_DEPTH-1 ----
#pragma unroll
  for (int p = 0; p < PIPE_DEPTH; p++) {
    cp_async8(slot0 + (p % NSLOTS) * (NTHREADS * 8),
              xbase + (size_t)min(t_begin + p, T_FRAMES - 1) * FSTRIDE);
    CP_COMMIT();
  }

  // ---- warm-up group: first 30 frames of the scan, no ring subtraction ----
  // c==0: real frames with exact ramp-up divisors (compile-time j == t).
  // c>0: halo frames; state stabilizes before emission (HALO=60 > 40).
  {
    const bool emit0 = (c == 0);
#pragma unroll
    for (int j = 0; j < 30; j++) {
      const int cj10 = (j < 1) ? 1 : (j > 10 ? 10 : j);
      const int cj30 = (j < 1) ? 1 : j;
      const float rc10 = 1.0f / (float)cj10;
      const float rc30 = 1.0f / (float)cj30;
      STEP(j, t_begin + j, rc10, rc30, false, emit0);
    }
    if (emit0) REDUCE_GROUP(t_begin);
  }

  // ---- steady groups: counts are constant 10 / 30 ----
  for (int tb = t_begin + 30; tb < chunk_end; tb += 30) {
    const bool emit = (tb + 29 >= chunk_start);  // block-uniform
#pragma unroll
    for (int j = 0; j < 30; j++) {
      STEP(j, tb + j, 0.1f, (1.0f / 30.0f), true, emit);
    }
    if (emit) REDUCE_GROUP(tb);
  }
}

extern "C" void kernel_launch(void* const* d_in, const int* in_sizes, int n_in,
                              void* d_out, int out_size) {
  (void)in_sizes; (void)n_in; (void)out_size;
  // hamming_sq_sum(25), periodic: sum((0.54 - 0.46*cos(2*pi*k/25))^2)
  double h = 0.0;
  for (int k = 0; k < 25; k++) {
    double w = 0.54 - 0.46 * cos(2.0 * M_PI * (double)k / 25.0);
    h += w * w;
  }
  // fold the /M (spectr) and /SAMPLE_RATE (welch) into one per-bin constant
  const float cA = (float)(h / 16000.0 / 10.0);

  const float* x = (const float*)d_in[0];
  float* out = (float*)d_out;
  ltsf_kernel<<<BATCH * CHUNKS, NTHREADS>>>(x, out, cA);
}

// round 9
// speedup vs baseline: 1.6125x; 1.1849x over previous
#include <cuda_runtime.h>
#include <stdint.h>
#include <math.h>

#define T_FRAMES   3000
#define F_BINS     201
#define FSTRIDE    (F_BINS * 2)         // floats per frame
#define BATCH      32
#define CHUNK      167
#define CHUNKS     18                   // 18*167 = 3006 >= 3000; last chunk short
#define HALO       40                   // exact history horizon (10 + 30)
#define NTHREADS   224
#define NWARPS     (NTHREADS / 32)
#define EPS_F      1e-5f
#define LOG10_2    0.30102999566398f    // log10(2)
#define PIPE_DEPTH 8                    // cp.async frames in flight
#define NSLOTS     10                   // smem ring slots (30 % 10 == 0, even)

__device__ __forceinline__ void cp_async8(uint32_t smem_addr, const float* gptr) {
  asm volatile("cp.async.ca.shared.global [%0], [%1], 8;\n"
               :: "r"(smem_addr), "l"(gptr));
}
#define CP_COMMIT() asm volatile("cp.async.commit_group;\n" ::: "memory")
#define CP_WAIT3()  asm volatile("cp.async.wait_group 3;\n" ::: "memory")

// One scan step. J compile-time (unrolled) so rings stay in registers and the
// smem slot index is an immediate. cp.async groups are PAIRS of frames:
// commit on odd J, wait_group 3 on even J (4 pair-groups in flight = 8 frames).
// ring_w stores (welch + EPS), so mean(ring) IS the epsilon-shifted arithmetic
// mean and no separate +EPS adds are needed anywhere.
#define STEP(J, TT, RC10, RC30, RC30K, DO_SUB, EMIT)                             \
  do {                                                                           \
    const int t_ = (TT);                                                         \
    if (((J) & 1) == 0) CP_WAIT3();                                              \
    float2 xv = stage[(J) % NSLOTS][tid];                                        \
    {                                                                            \
      const int tp_ = min(t_ + PIPE_DEPTH, T_FRAMES - 1);                        \
      cp_async8(slot0 + (((J) + PIPE_DEPTH) % NSLOTS) * (NTHREADS * 8),          \
                xbase + (size_t)tp_ * FSTRIDE);                                  \
    }                                                                            \
    if (((J) & 1) == 1) CP_COMMIT();                                             \
    const float s_t = (xv.x * xv.x + xv.y * xv.y) * Cf;                          \
    const float we_t = (t_ == 0) ? EPS_F : fmaf(sum_s, (RC10), EPS_F);           \
    const float lw2_t = __log2f(we_t);                                           \
    if (EMIT) {                                                                  \
      float contrib = 0.f;                                                       \
      if (active && t_ > 0) {                                                    \
        const float am = sum_we * (RC30);                                        \
        contrib = fmaf(__log2f(am), LOG10_2, -(sum_lw2 * (RC30K)));              \
      }                                                                          \
      buf[J][tid] = contrib;                                                     \
    }                                                                            \
    if (DO_SUB) {                                                                \
      const float we_old = ring_w[(J) % 30];                                     \
      sum_we  += we_t - we_old;                                                  \
      sum_lw2 += lw2_t - __log2f(we_old);                                        \
    } else {                                                                     \
      sum_we  += we_t;                                                           \
      sum_lw2 += lw2_t;                                                          \
    }                                                                            \
    ring_w[(J) % 30] = we_t;                                                     \
    sum_s += s_t - ring_s[(J) % 10];                                             \
    ring_s[(J) % 10] = s_t;                                                      \
  } while (0)

// Batched cross-thread reduction of one 30-frame group (block-uniform emit).
// Writes masked to [chunk_start, chunk_end): frames below chunk_start have
// incomplete history here (HALO=40 is exact, not 30-aligned); frames at or
// past chunk_end belong to the next chunk (or are past T_FRAMES).
#define REDUCE_GROUP(TB)                                                         \
  do {                                                                           \
    __syncthreads();                                                             \
    for (int j_ = warp; j_ < 30; j_ += NWARPS) {                                 \
      float v_ = 0.f;                                                            \
      _Pragma("unroll")                                                          \
      for (int i_ = 0; i_ < NTHREADS / 32; i_++)                                 \
        v_ += buf[j_][lane + 32 * i_];                                           \
      _Pragma("unroll")                                                          \
      for (int off_ = 16; off_ > 0; off_ >>= 1)                                  \
        v_ += __shfl_xor_sync(0xffffffffu, v_, off_);                            \
      const int tj_ = (TB) + j_;                                                 \
      if (lane == 0 && tj_ >= chunk_start && tj_ < chunk_end)                    \
        out[(size_t)b * T_FRAMES + tj_] = v_;                                    \
    }                                                                            \
    __syncthreads();                                                             \
  } while (0)

__global__ __launch_bounds__(NTHREADS, 4)
void ltsf_kernel(const float* __restrict__ x, float* __restrict__ out,
                 const float cA) {
  const int unit = blockIdx.x;
  const int b = unit / CHUNKS;
  const int c = unit % CHUNKS;
  const int chunk_start = c * CHUNK;
  const int chunk_end = min(chunk_start + CHUNK, T_FRAMES);
  const int t_begin = (c == 0) ? 0 : (chunk_start - HALO);

  const int tid  = threadIdx.x;
  const int f    = tid;
  const bool active = (f < F_BINS);
  const int lane = tid & 31;
  const int warp = tid >> 5;

  __shared__ float2 stage[NSLOTS][NTHREADS];  // cp.async ring (17.9 KB)
  __shared__ float  buf[30][NTHREADS];        // contrib tile (26.9 KB)

  // per-bin scale: interior bins doubled (welch one-sided spectrum)
  const float Cf = (f == 0 || f == F_BINS - 1) ? cA : 2.0f * cA;

  // inactive threads stream bin 0 (harmless; contrib is masked)
  const int fsel = active ? f : 0;
  const float* xbase =
      x + (size_t)b * T_FRAMES * FSTRIDE + (size_t)fsel * 2;
  const uint32_t slot0 = (uint32_t)__cvta_generic_to_shared(&stage[0][tid]);

  // register-resident ring buffers (indices compile-time via full unroll)
  float ring_s[10];
  float ring_w[30];
  float sum_s = 0.f, sum_we = 0.f, sum_lw2 = 0.f;
#pragma unroll
  for (int i = 0; i < 10; i++) ring_s[i] = 0.f;
#pragma unroll
  for (int i = 0; i < 30; i++) ring_w[i] = 0.f;

  // ---- pipeline prologue: 8 frames as 4 pair-groups ----
#pragma unroll
  for (int p = 0; p < PIPE_DEPTH; p += 2) {
    cp_async8(slot0 + (p % NSLOTS) * (NTHREADS * 8),
              xbase + (size_t)min(t_begin + p, T_FRAMES - 1) * FSTRIDE);
    cp_async8(slot0 + ((p + 1) % NSLOTS) * (NTHREADS * 8),
              xbase + (size_t)min(t_begin + p + 1, T_FRAMES - 1) * FSTRIDE);
    CP_COMMIT();
  }

  // ---- warm-up group: first 30 frames of the scan, no ring subtraction ----
  // c==0: real frames with exact ramp-up divisors (compile-time j == t).
  // c>0: halo frames; no emission (first emitted frames get >=40 history).
  {
    const bool emit0 = (c == 0);
#pragma unroll
    for (int j = 0; j < 30; j++) {
      const int cj10 = (j < 1) ? 1 : (j > 10 ? 10 : j);
      const int cj30 = (j < 1) ? 1 : j;
      const float rc10 = 1.0f / (float)cj10;
      const float rc30 = 1.0f / (float)cj30;
      STEP(j, t_begin + j, rc10, rc30, rc30 * LOG10_2, false, emit0);
    }
    if (emit0) REDUCE_GROUP(t_begin);
  }

  // ---- steady groups: counts are constant 10 / 30 ----
  for (int tb = t_begin + 30; tb < chunk_end; tb += 30) {
    const bool emit = (tb + 29 >= chunk_start);  // block-uniform
#pragma unroll
    for (int j = 0; j < 30; j++) {
      STEP(j, tb + j, 0.1f, (1.0f / 30.0f), (LOG10_2 / 30.0f), true, emit);
    }
    if (emit) REDUCE_GROUP(tb);
  }
}

extern "C" void kernel_launch(void* const* d_in, const int* in_sizes, int n_in,
                              void* d_out, int out_size) {
  (void)in_sizes; (void)n_in; (void)out_size;
  // hamming_sq_sum(25), periodic: sum((0.54 - 0.46*cos(2*pi*k/25))^2)
  double h = 0.0;
  for (int k = 0; k < 25; k++) {
    double w = 0.54 - 0.46 * cos(2.0 * M_PI * (double)k / 25.0);
    h += w * w;
  }
  // fold the /M (spectr) and /SAMPLE_RATE (welch) into one per-bin constant
  const float cA = (float)(h / 16000.0 / 10.0);

  const float* x = (const float*)d_in[0];
  float* out = (float*)d_out;
  ltsf_kernel<<<BATCH * CHUNKS, NTHREADS>>>(x, out, cA);
}

// round 10
// speedup vs baseline: 1.7238x; 1.0690x over previous
#include <cuda_runtime.h>
#include <stdint.h>
#include <math.h>

#define T_FRAMES   3000
#define F_BINS     201
#define FSTRIDE    (F_BINS * 2)         // floats per frame
#define BATCH      32
#define CHUNK      167
#define CHUNKS     18                   // 18*167 = 3006 >= 3000; last chunk short
#define HALO       40                   // exact history horizon (10 + 30)
#define NTHREADS   224
#define NWARPS     (NTHREADS / 32)
#define EPS_F      1e-5f
#define LOG10_2    0.30102999566398f    // log10(2)

__device__ __forceinline__ void cp_async8(uint32_t smem_addr, const float* gptr) {
  asm volatile("cp.async.ca.shared.global [%0], [%1], 8;\n"
               :: "r"(smem_addr), "l"(gptr));
}
#define CP_COMMIT() asm volatile("cp.async.commit_group;\n" ::: "memory")
#define CP_WAIT3()  asm volatile("cp.async.wait_group 3;\n" ::: "memory")

// Per-frame scan math (no global memory). J is an unroll immediate so all ring
// indices resolve to fixed registers. Inactive threads are masked by L10m==0
// (contrib FFMA self-zeroes), not by predicates. T0CHK (compile-time) guards
// the t==0 special case; it is only enabled in warm-up pair 0.
#define FRAME_MATH(J, xx, yy, RC10, RC30, RC30LM, DO_SUB, EMIT, T0CHK)           \
  do {                                                                           \
    const float s_t = fmaf(yy, yy, (xx) * (xx)) * Cf;                            \
    float we_t = fmaf(sum_s, (RC10), EPS_F);                                     \
    if (T0CHK) we_t = t0block ? EPS_F : we_t;                                    \
    const float lw2_t = __log2f(we_t);                                           \
    if (EMIT) {                                                                  \
      const float am = sum_we * (RC30);                                          \
      float contrib = fmaf(__log2f(am), L10m, -(sum_lw2 * (RC30LM)));            \
      if (T0CHK) contrib = t0block ? 0.f : contrib;                              \
      buf[J][tid] = contrib;                                                     \
    }                                                                            \
    if (DO_SUB) {                                                                \
      const float we_old = ring_w[(J) % 30];                                     \
      sum_we  += we_t - we_old;                                                  \
      sum_lw2 += lw2_t - __log2f(we_old);                                        \
    } else {                                                                     \
      sum_we  += we_t;                                                           \
      sum_lw2 += lw2_t;                                                          \
    }                                                                            \
    ring_w[(J) % 30] = we_t;                                                     \
    sum_s += s_t - ring_s[(J) % 10];                                             \
    ring_s[(J) % 10] = s_t;                                                      \
  } while (0)

// Steady pair (frames tb+2JP, tb+2JP+1). Prefetch address = xrow + immediate,
// so ptxas folds the offset into the LDGSTS instruction (xrow hoisted per
// group). No clamp: caller guarantees tb+38 <= T_FRAMES.
#define PAIR_BULK(JP)                                                            \
  do {                                                                           \
    CP_WAIT3();                                                                  \
    const float4 q = stage4[(JP) % 5][tid];                                      \
    cp_async8(slot0 + (((JP) + 4) % 5) * (NTHREADS * 16),                        \
              xrow + (size_t)(2 * (JP)) * FSTRIDE);                              \
    cp_async8(slot0 + (((JP) + 4) % 5) * (NTHREADS * 16) + 8,                    \
              xrow + (size_t)(2 * (JP) + 1) * FSTRIDE);                          \
    CP_COMMIT();                                                                 \
    FRAME_MATH(2*(JP),   q.x, q.y, 0.1f, (1.0f/30.0f), rc30Lm, true, true, false); \
    FRAME_MATH(2*(JP)+1, q.z, q.w, 0.1f, (1.0f/30.0f), rc30Lm, true, true, false); \
  } while (0)

// Tail pair: same math, prefetch clamped to the last frame (only the final
// chunk ever runs this; overrun frames compute garbage that is never written).
#define PAIR_TAIL(JP)                                                            \
  do {                                                                           \
    CP_WAIT3();                                                                  \
    const float4 q = stage4[(JP) % 5][tid];                                      \
    cp_async8(slot0 + (((JP) + 4) % 5) * (NTHREADS * 16),                        \
              xbase + (size_t)min(tb + 2*(JP) + 8, T_FRAMES - 1) * FSTRIDE);     \
    cp_async8(slot0 + (((JP) + 4) % 5) * (NTHREADS * 16) + 8,                    \
              xbase + (size_t)min(tb + 2*(JP) + 9, T_FRAMES - 1) * FSTRIDE);     \
    CP_COMMIT();                                                                 \
    FRAME_MATH(2*(JP),   q.x, q.y, 0.1f, (1.0f/30.0f), rc30Lm, true, true, false); \
    FRAME_MATH(2*(JP)+1, q.z, q.w, 0.1f, (1.0f/30.0f), rc30Lm, true, true, false); \
  } while (0)

// Warm-up pair with per-frame ramp divisors (compile-time after unroll).
// DO_SUB=false (rings hold zeros). EMIT only for chunk 0 (runtime-uniform).
#define PAIR_WARM(JP)                                                            \
  do {                                                                           \
    CP_WAIT3();                                                                  \
    const float4 q = stage4[(JP) % 5][tid];                                      \
    cp_async8(slot0 + (((JP) + 4) % 5) * (NTHREADS * 16),                        \
              xrow0 + (size_t)(2 * (JP)) * FSTRIDE);                             \
    cp_async8(slot0 + (((JP) + 4) % 5) * (NTHREADS * 16) + 8,                    \
              xrow0 + (size_t)(2 * (JP) + 1) * FSTRIDE);                         \
    CP_COMMIT();                                                                 \
    {                                                                            \
      const int jA = 2 * (JP);                                                   \
      const float rc10A = 1.0f / (float)((jA < 1) ? 1 : (jA > 10 ? 10 : jA));    \
      const float rc30A = 1.0f / (float)((jA < 1) ? 1 : jA);                     \
      FRAME_MATH(2*(JP), q.x, q.y, rc10A, rc30A, rc30A * L10m,                   \
                 false, emit0, ((JP) == 0));                                     \
      const int jB = 2 * (JP) + 1;                                               \
      const float rc10B = 1.0f / (float)((jB > 10) ? 10 : jB);                   \
      const float rc30B = 1.0f / (float)jB;                                      \
      FRAME_MATH(2*(JP)+1, q.z, q.w, rc10B, rc30B, rc30B * L10m,                 \
                 false, emit0, false);                                           \
    }                                                                            \
  } while (0)

// Batched cross-thread reduction of one 30-frame group. Writes masked to
// [chunk_start, chunk_end).
#define REDUCE_GROUP(TB)                                                         \
  do {                                                                           \
    __syncthreads();                                                             \
    for (int j_ = warp; j_ < 30; j_ += NWARPS) {                                 \
      float v_ = 0.f;                                                            \
      _Pragma("unroll")                                                          \
      for (int i_ = 0; i_ < NTHREADS / 32; i_++)                                 \
        v_ += buf[j_][lane + 32 * i_];                                           \
      _Pragma("unroll")                                                          \
      for (int off_ = 16; off_ > 0; off_ >>= 1)                                  \
        v_ += __shfl_xor_sync(0xffffffffu, v_, off_);                            \
      const int tj_ = (TB) + j_;                                                 \
      if (lane == 0 && tj_ >= chunk_start && tj_ < chunk_end)                    \
        out[(size_t)b * T_FRAMES + tj_] = v_;                                    \
    }                                                                            \
    __syncthreads();                                                             \
  } while (0)

__global__ __launch_bounds__(NTHREADS, 4)
void ltsf_kernel(const float* __restrict__ x, float* __restrict__ out,
                 const float cA) {
  const int unit = blockIdx.x;
  const int b = unit / CHUNKS;
  const int c = unit % CHUNKS;
  const int chunk_start = c * CHUNK;
  const int chunk_end = min(chunk_start + CHUNK, T_FRAMES);
  const int t_begin = (c == 0) ? 0 : (chunk_start - HALO);
  const bool t0block = (c == 0);

  const int tid  = threadIdx.x;
  const int f    = tid;
  const bool active = (f < F_BINS);
  const int lane = tid & 31;
  const int warp = tid >> 5;

  __shared__ float4 stage4[5][NTHREADS];   // cp.async pair-slot ring (17.9 KB)
  __shared__ float  buf[30][NTHREADS];     // contrib tile (26.9 KB)

  // per-bin scale: interior bins doubled (welch one-sided spectrum)
  const float Cf = (f == 0 || f == F_BINS - 1) ? cA : 2.0f * cA;
  // masking constants: inactive threads produce exactly 0 contrib
  const float L10m   = active ? LOG10_2 : 0.f;
  const float rc30Lm = L10m * (1.0f / 30.0f);

  // inactive threads stream bin 0 (harmless; contrib masked to 0)
  const int fsel = active ? f : 0;
  const float* xbase =
      x + (size_t)b * T_FRAMES * FSTRIDE + (size_t)fsel * 2;
  const uint32_t slot0 = (uint32_t)__cvta_generic_to_shared(&stage4[0][tid]);

  // register-resident ring buffers (indices compile-time via full unroll)
  float ring_s[10];
  float ring_w[30];
  float sum_s = 0.f, sum_we = 0.f, sum_lw2 = 0.f;
#pragma unroll
  for (int i = 0; i < 10; i++) ring_s[i] = 0.f;
#pragma unroll
  for (int i = 0; i < 30; i++) ring_w[i] = 0.f;

  // ---- prologue: frames t_begin..t_begin+7 as 4 pair-groups (in-bounds:
  //      t_begin+7 <= 2806 always) ----
#pragma unroll
  for (int p = 0; p < 4; p++) {
    cp_async8(slot0 + p * (NTHREADS * 16),
              xbase + (size_t)(t_begin + 2 * p) * FSTRIDE);
    cp_async8(slot0 + p * (NTHREADS * 16) + 8,
              xbase + (size_t)(t_begin + 2 * p + 1) * FSTRIDE);
    CP_COMMIT();
  }

  // ---- warm-up group (30 frames, ramp divisors, no ring subtraction) ----
  // Prefetch targets <= t_begin+37 <= 2836 < T_FRAMES: no clamp needed.
  {
    const bool emit0 = t0block;
    const float* xrow0 = xbase + (size_t)(t_begin + 8) * FSTRIDE;
#pragma unroll
    for (int jp = 0; jp < 15; jp++) PAIR_WARM(jp);
    if (emit0) REDUCE_GROUP(t_begin);
  }

  // ---- steady bulk: all prefetches provably in-bounds (tb+38 <= T) ----
  int tb = t_begin + 30;
  for (; tb < chunk_end && tb + 38 <= T_FRAMES; tb += 30) {
    const float* xrow = xbase + (size_t)(tb + 8) * FSTRIDE;
#pragma unroll
    for (int jp = 0; jp < 15; jp++) PAIR_BULK(jp);
    REDUCE_GROUP(tb);
  }

  // ---- clamped tail (last chunk only) ----
  for (; tb < chunk_end; tb += 30) {
#pragma unroll
    for (int jp = 0; jp < 15; jp++) PAIR_TAIL(jp);
    REDUCE_GROUP(tb);
  }
}

extern "C" void kernel_launch(void* const* d_in, const int* in_sizes, int n_in,
                              void* d_out, int out_size) {
  (void)in_sizes; (void)n_in; (void)out_size;
  // hamming_sq_sum(25), periodic: sum((0.54 - 0.46*cos(2*pi*k/25))^2)
  double h = 0.0;
  for (int k = 0; k < 25; k++) {
    double w = 0.54 - 0.46 * cos(2.0 * M_PI * (double)k / 25.0);
    h += w * w;
  }
  // fold the /M (spectr) and /SAMPLE_RATE (welch) into one per-bin constant
  const float cA = (float)(h / 16000.0 / 10.0);

  const float* x = (const float*)d_in[0];
  float* out = (float*)d_out;
  ltsf_kernel<<<BATCH * CHUNKS, NTHREADS>>>(x, out, cA);
}